// round 11
// baseline (speedup 1.0000x reference)
#include <cuda_runtime.h>
#include <cuda_fp16.h>
#include <cstdint>

#define ALPHA 0.2f

// Aggregated edge features scratch: [128*75, 192] = 7.37 MB (static, allowed)
static __device__ float g_agg[9600 * 192];
// Pre-converted fp16 node weights, already in node-SMEM layout (u32 = f16x2, stride 132)
static __device__ uint4 g_w1h[208 * 132 / 4];   // 195x256 valid, zero-padded
static __device__ uint4 g_w2h[256 * 132 / 4];

__device__ __forceinline__ float lrelu(float v) { return v > 0.0f ? v : ALPHA * v; }

// ---- packed fp32 helpers ----
#define FFMA2(acc, a, b) \
    asm("fma.rn.f32x2 %0, %1, %2, %0;" : "+l"(acc) : "l"(a), "l"(b))
__device__ __forceinline__ float2 unpack2(unsigned long long v) {
    float2 r;
    asm("mov.b64 {%0, %1}, %2;" : "=f"(r.x), "=f"(r.y) : "l"(v));
    return r;
}
__device__ __forceinline__ unsigned long long pack2(float lo, float hi) {
    unsigned long long r;
    asm("mov.b64 %0, {%1, %2};" : "=l"(r) : "f"(lo), "f"(hi));
    return r;
}
// pack two f32 -> f16x2 word: halves[0] = lo, halves[1] = hi
__device__ __forceinline__ uint32_t cvt_f16x2(float hi, float lo) {
    uint32_t d;
    asm("cvt.rn.f16x2.f32 %0, %1, %2;" : "=r"(d) : "f"(hi), "f"(lo));
    return d;
}
__device__ __forceinline__ uint32_t smem_u32(const void* p) {
    uint32_t a;
    asm("{ .reg .u64 t; cvta.to.shared.u64 t, %1; cvt.u32.u64 %0, t; }"
        : "=r"(a) : "l"(p));
    return a;
}

// ---- warp-level tensor core (sm_80+ path; valid on plain sm_103) ----
#define LDSM_X4(a0, a1, a2, a3, addr) \
    asm volatile("ldmatrix.sync.aligned.m8n8.x4.shared.b16 {%0,%1,%2,%3}, [%4];" \
                 : "=r"(a0), "=r"(a1), "=r"(a2), "=r"(a3) : "r"(addr))
#define LDSM_X2T(b0, b1, addr) \
    asm volatile("ldmatrix.sync.aligned.m8n8.x2.trans.shared.b16 {%0,%1}, [%2];" \
                 : "=r"(b0), "=r"(b1) : "r"(addr))
#define MMA16816(c, a0, a1, a2, a3, b0, b1) \
    asm volatile("mma.sync.aligned.m16n8k16.row.col.f32.f16.f16.f32 " \
                 "{%0,%1,%2,%3}, {%4,%5,%6,%7}, {%8,%9}, {%0,%1,%2,%3};" \
                 : "+f"((c)[0]), "+f"((c)[1]), "+f"((c)[2]), "+f"((c)[3]) \
                 : "r"(a0), "r"(a1), "r"(a2), "r"(a3), "r"(b0), "r"(b1))

// ================= PREP KERNEL: fn weights -> fp16 layout =================
__global__ void __launch_bounds__(256)
prep_kernel(const float* __restrict__ w1, const float* __restrict__ w2)
{
    int i = blockIdx.x * 256 + threadIdx.x;
    if (i < 208 * 132) {
        int k = i / 132, u = i - k * 132;
        uint32_t v = 0u;
        if (k < 195 && u < 128)
            v = cvt_f16x2(w1[(size_t)k * 256 + 2 * u + 1], w1[(size_t)k * 256 + 2 * u]);
        ((uint32_t*)g_w1h)[i] = v;
    }
    if (i < 256 * 132) {
        int k = i / 132, u = i - k * 132;
        uint32_t v = 0u;
        if (u < 128)
            v = cvt_f16x2(w2[(size_t)k * 256 + 2 * u + 1], w2[(size_t)k * 256 + 2 * u]);
        ((uint32_t*)g_w2h)[i] = v;
    }
}

// ================= EDGE KERNEL (2 bi per iteration) =================
// SMEM bytes:
#define BW2 0        // W2 fp16 [96 k][168 n-stride]  (160 used)  = 32256 B
#define BW3 32256    // W3 fp16 [160 k][200 n-stride] (192 used)  = 64000 B
#define BH1 96256    // h1 fp16 [160 m][104 k-stride] (2 slots of 80) = 33280 B
#define BH2 129536   // h2 fp16 [160 m][168 k-stride] = 53760 B
// f32 region (float indices; byte base 183296)
#define OF_W1 45824  // 672
#define OF_B2 46496  // 160
#define OF_B3 46656  // 192
#define OF_UI 46848  // 2 x 96
#define OF_XJ 47040  // 2 x 228
#define OF_D  47496  // 2 x 76
#define SMEM1_FL 47648
#define SMEM1_BYTES (SMEM1_FL * 4)   // 190592
#define H1B32 (BH1 / 4)
#define H2B32 (BH2 / 4)

__global__ void __launch_bounds__(256, 1)
edge_kernel(const float* __restrict__ x,
            const float* __restrict__ w1, const float* __restrict__ b1,
            const float* __restrict__ w2, const float* __restrict__ b2,
            const float* __restrict__ w3, const float* __restrict__ b3)
{
    extern __shared__ float s[];
    uint32_t* s32 = (uint32_t*)s;
    __half* sh = (__half*)s;
    const int tid = threadIdx.x;
    const int wid = tid >> 5;
    const int lane = tid & 31;
    const uint32_t sbase = smem_u32(s);

    for (int i = tid; i < 672; i += 256) s[OF_W1 + i] = w1[i];
    for (int i = tid; i < 160; i += 256) s[OF_B2 + i] = b2[i];
    for (int i = tid; i < 192; i += 256) s[OF_B3 + i] = b3[i];
    for (int idx = tid; idx < 96 * 160; idx += 256) {
        int k = idx / 160, n = idx - k * 160;
        sh[k * 168 + n] = __float2half(w2[idx]);
    }
    for (int idx = tid; idx < 160 * 192; idx += 256) {
        int k = idx / 192, n = idx - k * 192;
        sh[BW3 / 2 + k * 200 + n] = __float2half(w3[idx]);
    }
    // zero h1 pad rows 75..79 and 155..159 (never rewritten)
    for (int idx = tid; idx < 10 * 52; idx += 256) {
        int rr = idx / 52;
        int row = (rr < 5) ? (75 + rr) : (150 + rr);
        s32[H1B32 + row * 52 + (idx % 52)] = 0u;
    }
    __syncthreads();

    const int nt1 = (wid < 4) ? 3 : 2;
    int n1[3], n2[3];
    #pragma unroll
    for (int j = 0; j < 3; j++) { n1[j] = 8 * wid + 64 * j; n2[j] = 8 * wid + 64 * j; }
    const int lA = lane & 15, gA = lane >> 4;
    const int lB = lane & 15;
    const int qr = lane >> 2, qc = lane & 3;
    const uint32_t a1base = sbase + BH1 + (uint32_t)(lA * 104 + gA * 8) * 2;
    const uint32_t a2base = sbase + BH2 + (uint32_t)(lA * 168 + gA * 8) * 2;
    const uint32_t b2base = sbase + BW2 + (uint32_t)(lB * 168) * 2;
    const uint32_t b3base = sbase + BW3 + (uint32_t)(lB * 200) * 2;
    float e1b0[3], e1b1[3], e2b0[3], e2b1[3];
    #pragma unroll
    for (int j = 0; j < 3; j++) {
        if (j < nt1) {
            e1b0[j] = s[OF_B2 + n1[j] + 2 * qc];
            e1b1[j] = s[OF_B2 + n1[j] + 2 * qc + 1];
        } else { e1b0[j] = 0.f; e1b1[j] = 0.f; }
        e2b0[j] = s[OF_B3 + n2[j] + 2 * qc];
        e2b1[j] = s[OF_B3 + n2[j] + 2 * qc + 1];
    }

    // ---- Hoist loop-invariant B fragments into registers ----
    uint32_t bf2[6][3][2];
    uint32_t bf3[10][3][2];
    #pragma unroll
    for (int k = 0; k < 6; k++)
        #pragma unroll
        for (int j = 0; j < 3; j++) {
            if (j < nt1) { LDSM_X2T(bf2[k][j][0], bf2[k][j][1], b2base + k * 5376 + n1[j] * 2); }
            else { bf2[k][j][0] = 0u; bf2[k][j][1] = 0u; }
        }
    #pragma unroll
    for (int k = 0; k < 10; k++)
        #pragma unroll
        for (int j = 0; j < 3; j++)
            LDSM_X2T(bf3[k][j][0], bf3[k][j][1], b3base + k * 6400 + n2[j] * 2);

    for (int p = blockIdx.x; p < 4800; p += gridDim.x) {
        const int bi0 = 2 * p;

        // ---- Phase A: XJ/D for both slots (150 thr) + UI for both (192 thr) ----
        if (tid < 150) {
            int q = tid / 75, j = tid - q * 75;
            int bi = bi0 + q;
            int b = bi / 75, i = bi - b * 75;
            const float* xb = x + b * 225;
            float xi0 = xb[i * 3], xi1 = xb[i * 3 + 1], xi2 = xb[i * 3 + 2];
            float a0 = xb[j * 3], a1 = xb[j * 3 + 1], a2 = xb[j * 3 + 2];
            float* XJ = s + OF_XJ + q * 228;
            XJ[3 * j + 0] = a0; XJ[3 * j + 1] = a1; XJ[3 * j + 2] = a2;
            float d0 = (a0 - xi0) + 1e-12f;
            float d1 = (a1 - xi1) + 1e-12f;
            float d2 = (a2 - xi2) + 1e-12f;
            s[OF_D + q * 76 + j] = sqrtf(d0 * d0 + d1 * d1 + d2 * d2);
        }
        if (tid < 192) {
            int q = tid / 96, c = tid - q * 96;
            int bi = bi0 + q;
            int b = bi / 75, i = bi - b * 75;
            const float* xb = x + b * 225;
            float xi0 = xb[i * 3], xi1 = xb[i * 3 + 1], xi2 = xb[i * 3 + 2];
            s[OF_UI + q * 96 + c] = b1[c] + xi0 * s[OF_W1 + c]
                                          + xi1 * s[OF_W1 + 96 + c]
                                          + xi2 * s[OF_W1 + 192 + c];
        }
        __syncthreads();

        // ---- Phase B: h1 for both slots (150 valid rows) ----
        for (int idx = tid; idx < 150 * 48; idx += 256) {
            int rr = idx / 48, w = idx - rr * 48;
            int q = (rr >= 75) ? 1 : 0;
            int r = rr - q * 75;
            const float* XJ = s + OF_XJ + q * 228;
            float xj0 = XJ[3 * r + 0];
            float xj1 = XJ[3 * r + 1];
            float xj2 = XJ[3 * r + 2];
            float dj  = s[OF_D + q * 76 + r];
            unsigned long long v =
                *(const unsigned long long*)(s + OF_UI + q * 96 + 2 * w);
            FFMA2(v, pack2(xj0, xj0), *(const unsigned long long*)(s + OF_W1 + 288 + 2 * w));
            FFMA2(v, pack2(xj1, xj1), *(const unsigned long long*)(s + OF_W1 + 384 + 2 * w));
            FFMA2(v, pack2(xj2, xj2), *(const unsigned long long*)(s + OF_W1 + 480 + 2 * w));
            FFMA2(v, pack2(dj, dj),   *(const unsigned long long*)(s + OF_W1 + 576 + 2 * w));
            float2 vf = unpack2(v);
            s32[H1B32 + (q * 80 + r) * 52 + w] = cvt_f16x2(lrelu(vf.y), lrelu(vf.x));
        }
        __syncthreads();

        // ---- MMA1: both halves; D1 = h1 @ W2 ; epi -> h2 fp16 ----
        #pragma unroll
        for (int h = 0; h < 2; h++) {
            const uint32_t aoff = (uint32_t)h * 16640;
            float acc[5][3][4];
            #pragma unroll
            for (int m = 0; m < 5; m++)
                #pragma unroll
                for (int j = 0; j < 3; j++)
                    { acc[m][j][0]=0.f; acc[m][j][1]=0.f; acc[m][j][2]=0.f; acc[m][j][3]=0.f; }
            #pragma unroll
            for (int k = 0; k < 6; k++) {
                #pragma unroll
                for (int m = 0; m < 5; m++) {
                    uint32_t a0, a1, a2, a3;
                    LDSM_X4(a0, a1, a2, a3, a1base + aoff + m * 3328 + k * 32);
                    #pragma unroll
                    for (int j = 0; j < 3; j++)
                        if (j < nt1) MMA16816(acc[m][j], a0, a1, a2, a3, bf2[k][j][0], bf2[k][j][1]);
                }
            }
            #pragma unroll
            for (int m = 0; m < 5; m++) {
                int r1 = h * 80 + m * 16 + qr, r2 = r1 + 8;
                #pragma unroll
                for (int j = 0; j < 3; j++)
                    if (j < nt1) {
                        uint32_t u = n1[j] / 2 + qc;
                        s32[H2B32 + r1 * 84 + u] =
                            cvt_f16x2(lrelu(acc[m][j][1] + e1b1[j]),
                                      lrelu(acc[m][j][0] + e1b0[j]));
                        s32[H2B32 + r2 * 84 + u] =
                            cvt_f16x2(lrelu(acc[m][j][3] + e1b1[j]),
                                      lrelu(acc[m][j][2] + e1b0[j]));
                    }
            }
        }
        __syncthreads();

        // ---- MMA2: both halves; D2 = h2 @ W3 ; epi -> column sums -> g_agg ----
        #pragma unroll
        for (int h = 0; h < 2; h++) {
            const uint32_t aoff = (uint32_t)h * 26880;
            float acc[5][3][4];
            #pragma unroll
            for (int m = 0; m < 5; m++)
                #pragma unroll
                for (int j = 0; j < 3; j++)
                    { acc[m][j][0]=0.f; acc[m][j][1]=0.f; acc[m][j][2]=0.f; acc[m][j][3]=0.f; }
            #pragma unroll
            for (int k = 0; k < 10; k++) {
                #pragma unroll
                for (int m = 0; m < 5; m++) {
                    uint32_t a0, a1, a2, a3;
                    LDSM_X4(a0, a1, a2, a3, a2base + aoff + m * 5376 + k * 32);
                    #pragma unroll
                    for (int j = 0; j < 3; j++)
                        MMA16816(acc[m][j], a0, a1, a2, a3, bf3[k][j][0], bf3[k][j][1]);
                }
            }
            float cs0[3] = {0.f, 0.f, 0.f}, cs1[3] = {0.f, 0.f, 0.f};
            #pragma unroll
            for (int m = 0; m < 5; m++) {
                bool ok2 = (m * 16 + 8 + qr) < 75;
                #pragma unroll
                for (int j = 0; j < 3; j++) {
                    cs0[j] += lrelu(acc[m][j][0] + e2b0[j]);
                    cs1[j] += lrelu(acc[m][j][1] + e2b1[j]);
                    if (ok2) {
                        cs0[j] += lrelu(acc[m][j][2] + e2b0[j]);
                        cs1[j] += lrelu(acc[m][j][3] + e2b1[j]);
                    }
                }
            }
            #pragma unroll
            for (int j = 0; j < 3; j++) {
                #pragma unroll
                for (int d = 4; d < 32; d <<= 1) {
                    cs0[j] += __shfl_xor_sync(0xFFFFFFFFu, cs0[j], d);
                    cs1[j] += __shfl_xor_sync(0xFFFFFFFFu, cs1[j], d);
                }
            }
            if (lane < 4) {
                float* gp = g_agg + (size_t)(bi0 + h) * 192;
                #pragma unroll
                for (int j = 0; j < 3; j++) {
                    gp[n2[j] + 2 * lane]     = cs0[j];
                    gp[n2[j] + 2 * lane + 1] = cs1[j];
                }
            }
        }
        // No trailing barrier: next Phase A writes (XJ/D/UI) were last read in
        // Phase B (two barriers back); next Phase B h1 writes are fenced by the
        // Phase A barrier; next MMA1 h2 writes are fenced by the Phase B barrier,
        // which every thread reaches only after finishing its own MMA2.
    }
}

// ================= NODE KERNEL — HMMA =================
#define BWN   0
#define BH1N  135168
#define BYN   168960
#define OFN_B1 50688
#define OFN_B2 50944
#define OFN_W3 51200
#define OFN_B3 51968
#define SMEM2_FL 51972
#define SMEM2_BYTES (SMEM2_FL * 4)
#define H1NU (BH1N / 4)
#define YNU  (BYN / 4)

__global__ void __launch_bounds__(256, 1)
node_kernel(const float* __restrict__ x,
            const float* __restrict__ b1,
            const float* __restrict__ b2,
            const float* __restrict__ w3, const float* __restrict__ b3,
            float* __restrict__ out)
{
    extern __shared__ float s[];
    uint32_t* s32 = (uint32_t*)s;
    __half* sh = (__half*)s;
    const int tid = threadIdx.x;
    const int wid = tid >> 5;
    const int lane = tid & 31;
    const uint32_t sbase = smem_u32(s);
    const int row0 = blockIdx.x * 64;

    const int lA = lane & 15, gA = lane >> 4;
    const int lB = lane & 15;
    const int qr = lane >> 2, qc = lane & 3;
    const int n0 = 32 * wid;
    const uint32_t aYbase  = sbase + BYN  + (uint32_t)(lA * 216 + gA * 8) * 2;
    const uint32_t aH1base = sbase + BH1N + (uint32_t)(lA * 264 + gA * 8) * 2;
    const uint32_t bWbase  = sbase + BWN  + (uint32_t)(lB * 264) * 2;

    for (int i = tid; i < 256; i += 256) s[OFN_B1 + i] = b1[i];
    for (int i = tid; i < 256; i += 256) s[OFN_B2 + i] = b2[i];
    for (int i = tid; i < 768; i += 256) s[OFN_W3 + i] = w3[i];
    if (tid < 3) s[OFN_B3 + tid] = b3[tid];

    for (int idx = tid; idx < 64 * 108; idx += 256) {
        int r = idx / 108, u = idx - r * 108;
        int gr = row0 + r;
        uint32_t v;
        if (u < 96) {
            const float* gp = g_agg + (size_t)gr * 192 + 2 * u;
            v = cvt_f16x2(gp[1], gp[0]);
        } else if (u == 96) {
            v = cvt_f16x2(x[gr * 3 + 1], x[gr * 3 + 0]);
        } else if (u == 97) {
            v = cvt_f16x2(0.f, x[gr * 3 + 2]);
        } else v = 0u;
        s32[YNU + r * 108 + u] = v;
    }
    {
        uint4* d = (uint4*)s32;
        for (int i = tid; i < 208 * 132 / 4; i += 256) d[i] = g_w1h[i];
    }
    __syncthreads();

    // ---- Phase 1: h1[64][256] = lrelu(y @ W1 + b1), K = 208 ----
    {
        float acc[4][4][4];
        #pragma unroll
        for (int m = 0; m < 4; m++)
            #pragma unroll
            for (int j = 0; j < 4; j++)
                { acc[m][j][0]=0.f; acc[m][j][1]=0.f; acc[m][j][2]=0.f; acc[m][j][3]=0.f; }
        #pragma unroll
        for (int kc = 0; kc < 13; kc++) {
            uint32_t bf[4][2];
            #pragma unroll
            for (int j = 0; j < 4; j++)
                LDSM_X2T(bf[j][0], bf[j][1], bWbase + kc * 8448 + (n0 + 8 * j) * 2);
            #pragma unroll
            for (int m = 0; m < 4; m++) {
                uint32_t a0, a1, a2, a3;
                LDSM_X4(a0, a1, a2, a3, aYbase + m * 6912 + kc * 32);
                #pragma unroll
                for (int j = 0; j < 4; j++)
                    MMA16816(acc[m][j], a0, a1, a2, a3, bf[j][0], bf[j][1]);
            }
        }
        #pragma unroll
        for (int m = 0; m < 4; m++) {
            int r1 = m * 16 + qr, r2 = r1 + 8;
            #pragma unroll
            for (int j = 0; j < 4; j++) {
                float bb0 = s[OFN_B1 + n0 + 8 * j + 2 * qc];
                float bb1 = s[OFN_B1 + n0 + 8 * j + 2 * qc + 1];
                uint32_t u = n0 / 2 + 4 * j + qc;
                s32[H1NU + r1 * 132 + u] =
                    cvt_f16x2(lrelu(acc[m][j][1] + bb1), lrelu(acc[m][j][0] + bb0));
                s32[H1NU + r2 * 132 + u] =
                    cvt_f16x2(lrelu(acc[m][j][3] + bb1), lrelu(acc[m][j][2] + bb0));
            }
        }
    }
    __syncthreads();

    {
        uint4* d = (uint4*)s32;
        for (int i = tid; i < 256 * 132 / 4; i += 256) d[i] = g_w2h[i];
    }
    __syncthreads();

    // ---- Phase 2: h2[64][256] = lrelu(h1 @ W2 + b2), K = 256 ----
    {
        float acc[4][4][4];
        #pragma unroll
        for (int m = 0; m < 4; m++)
            #pragma unroll
            for (int j = 0; j < 4; j++)
                { acc[m][j][0]=0.f; acc[m][j][1]=0.f; acc[m][j][2]=0.f; acc[m][j][3]=0.f; }
        #pragma unroll
        for (int kc = 0; kc < 16; kc++) {
            uint32_t bf[4][2];
            #pragma unroll
            for (int j = 0; j < 4; j++)
                LDSM_X2T(bf[j][0], bf[j][1], bWbase + kc * 8448 + (n0 + 8 * j) * 2);
            #pragma unroll
            for (int m = 0; m < 4; m++) {
                uint32_t a0, a1, a2, a3;
                LDSM_X4(a0, a1, a2, a3, aH1base + m * 8448 + kc * 32);
                #pragma unroll
                for (int j = 0; j < 4; j++)
                    MMA16816(acc[m][j], a0, a1, a2, a3, bf[j][0], bf[j][1]);
            }
        }
        #pragma unroll
        for (int m = 0; m < 4; m++) {
            int r1 = m * 16 + qr, r2 = r1 + 8;
            #pragma unroll
            for (int j = 0; j < 4; j++) {
                float bb0 = s[OFN_B2 + n0 + 8 * j + 2 * qc];
                float bb1 = s[OFN_B2 + n0 + 8 * j + 2 * qc + 1];
                uint32_t u = n0 / 2 + 4 * j + qc;
                s32[YNU + r1 * 132 + u] =
                    cvt_f16x2(lrelu(acc[m][j][1] + bb1), lrelu(acc[m][j][0] + bb0));
                s32[YNU + r2 * 132 + u] =
                    cvt_f16x2(lrelu(acc[m][j][3] + bb1), lrelu(acc[m][j][2] + bb0));
            }
        }
    }
    __syncthreads();

    // ---- Phase 3: out[64][3] = h2 @ W3 + b3 (half2-paired fp32) ----
    if (tid < 192) {
        int r = tid / 3, o = tid - r * 3;
        const __half2* hr = (const __half2*)(sh + BYN / 2 + r * 264);
        float a = s[OFN_B3 + o];
        #pragma unroll 8
        for (int k2 = 0; k2 < 128; k2++) {
            float2 h = __half22float2(hr[k2]);
            a += h.x * s[OFN_W3 + 6 * k2 + o] + h.y * s[OFN_W3 + 6 * k2 + 3 + o];
        }
        out[(row0 + r) * 3 + o] = a;
    }
}

extern "C" void kernel_launch(void* const* d_in, const int* in_sizes, int n_in,
                              void* d_out, int out_size)
{
    const float* x    = (const float*)d_in[0];
    const float* few1 = (const float*)d_in[1];
    const float* feb1 = (const float*)d_in[2];
    const float* few2 = (const float*)d_in[3];
    const float* feb2 = (const float*)d_in[4];
    const float* few3 = (const float*)d_in[5];
    const float* feb3 = (const float*)d_in[6];
    const float* fnw1 = (const float*)d_in[7];
    const float* fnb1 = (const float*)d_in[8];
    const float* fnw2 = (const float*)d_in[9];
    const float* fnb2 = (const float*)d_in[10];
    const float* fnw3 = (const float*)d_in[11];
    const float* fnb3 = (const float*)d_in[12];
    float* out = (float*)d_out;

    cudaFuncSetAttribute(edge_kernel, cudaFuncAttributeMaxDynamicSharedMemorySize, SMEM1_BYTES);
    cudaFuncSetAttribute(node_kernel, cudaFuncAttributeMaxDynamicSharedMemorySize, SMEM2_BYTES);

    prep_kernel<<<132, 256>>>(fnw1, fnw2);
    edge_kernel<<<148, 256, SMEM1_BYTES>>>(x, few1, feb1, few2, feb2, few3, feb3);
    node_kernel<<<150, 256, SMEM2_BYTES>>>(x, fnb1, fnb2, fnw3, fnb3, out);
}

// round 12
// speedup vs baseline: 1.0177x; 1.0177x over previous
#include <cuda_runtime.h>
#include <cuda_fp16.h>
#include <cstdint>

#define ALPHA 0.2f

// Aggregated edge features scratch: [128*75, 192] = 7.37 MB (static, allowed)
static __device__ float g_agg[9600 * 192];
// Pre-converted fp16 node weights, already in node-SMEM layout (u32 = f16x2, stride 132)
static __device__ uint4 g_w1h[208 * 132 / 4];   // 195x256 valid, zero-padded
static __device__ uint4 g_w2h[256 * 132 / 4];

__device__ __forceinline__ float lrelu(float v) { return v > 0.0f ? v : ALPHA * v; }

// ---- packed fp32 helpers ----
#define FFMA2(acc, a, b) \
    asm("fma.rn.f32x2 %0, %1, %2, %0;" : "+l"(acc) : "l"(a), "l"(b))
__device__ __forceinline__ float2 unpack2(unsigned long long v) {
    float2 r;
    asm("mov.b64 {%0, %1}, %2;" : "=f"(r.x), "=f"(r.y) : "l"(v));
    return r;
}
__device__ __forceinline__ unsigned long long pack2(float lo, float hi) {
    unsigned long long r;
    asm("mov.b64 %0, {%1, %2};" : "=l"(r) : "f"(lo), "f"(hi));
    return r;
}
// pack two f32 -> f16x2 word: halves[0] = lo, halves[1] = hi
__device__ __forceinline__ uint32_t cvt_f16x2(float hi, float lo) {
    uint32_t d;
    asm("cvt.rn.f16x2.f32 %0, %1, %2;" : "=r"(d) : "f"(hi), "f"(lo));
    return d;
}
__device__ __forceinline__ uint32_t smem_u32(const void* p) {
    uint32_t a;
    asm("{ .reg .u64 t; cvta.to.shared.u64 t, %1; cvt.u32.u64 %0, t; }"
        : "=r"(a) : "l"(p));
    return a;
}

// ---- warp-level tensor core (sm_80+ path; valid on plain sm_103) ----
#define LDSM_X4(a0, a1, a2, a3, addr) \
    asm volatile("ldmatrix.sync.aligned.m8n8.x4.shared.b16 {%0,%1,%2,%3}, [%4];" \
                 : "=r"(a0), "=r"(a1), "=r"(a2), "=r"(a3) : "r"(addr))
#define LDSM_X2T(b0, b1, addr) \
    asm volatile("ldmatrix.sync.aligned.m8n8.x2.trans.shared.b16 {%0,%1}, [%2];" \
                 : "=r"(b0), "=r"(b1) : "r"(addr))
#define MMA16816(c, a0, a1, a2, a3, b0, b1) \
    asm volatile("mma.sync.aligned.m16n8k16.row.col.f32.f16.f16.f32 " \
                 "{%0,%1,%2,%3}, {%4,%5,%6,%7}, {%8,%9}, {%0,%1,%2,%3};" \
                 : "+f"((c)[0]), "+f"((c)[1]), "+f"((c)[2]), "+f"((c)[3]) \
                 : "r"(a0), "r"(a1), "r"(a2), "r"(a3), "r"(b0), "r"(b1))

// ================= PREP KERNEL: fn weights -> fp16 layout =================
__global__ void __launch_bounds__(256)
prep_kernel(const float* __restrict__ w1, const float* __restrict__ w2)
{
    int i = blockIdx.x * 256 + threadIdx.x;
    if (i < 208 * 132) {
        int k = i / 132, u = i - k * 132;
        uint32_t v = 0u;
        if (k < 195 && u < 128)
            v = cvt_f16x2(w1[(size_t)k * 256 + 2 * u + 1], w1[(size_t)k * 256 + 2 * u]);
        ((uint32_t*)g_w1h)[i] = v;
    }
    if (i < 256 * 132) {
        int k = i / 132, u = i - k * 132;
        uint32_t v = 0u;
        if (u < 128)
            v = cvt_f16x2(w2[(size_t)k * 256 + 2 * u + 1], w2[(size_t)k * 256 + 2 * u]);
        ((uint32_t*)g_w2h)[i] = v;
    }
}

// ================= EDGE KERNEL (R10 proven version) =================
#define BW2 0        // W2 fp16 [96 k][168 n-stride]  (160 used)  = 32256 B
#define BW3 32256    // W3 fp16 [160 k][200 n-stride] (192 used)  = 64000 B
#define BH1 96256    // h1 fp16 [80 m][104 k-stride]  (96 used)   = 16640 B
#define BH2 112896   // h2 fp16 [80 m][168 k-stride]  (160 used)  = 26880 B
#define OF_W1 34944  // 672
#define OF_B2 35616  // 160
#define OF_B3 35776  // 192
#define OF_UI 35968  // 96
#define OF_XJ 36064  // 228
#define OF_D  36292  // 76
#define SMEM1_FL 36368
#define SMEM1_BYTES (SMEM1_FL * 4)
#define H1B32 (BH1 / 4)
#define H2B32 (BH2 / 4)

__global__ void __launch_bounds__(256, 1)
edge_kernel(const float* __restrict__ x,
            const float* __restrict__ w1, const float* __restrict__ b1,
            const float* __restrict__ w2, const float* __restrict__ b2,
            const float* __restrict__ w3, const float* __restrict__ b3)
{
    extern __shared__ float s[];
    uint32_t* s32 = (uint32_t*)s;
    __half* sh = (__half*)s;
    const int tid = threadIdx.x;
    const int wid = tid >> 5;
    const int lane = tid & 31;
    const uint32_t sbase = smem_u32(s);

    for (int i = tid; i < 672; i += 256) s[OF_W1 + i] = w1[i];
    for (int i = tid; i < 160; i += 256) s[OF_B2 + i] = b2[i];
    for (int i = tid; i < 192; i += 256) s[OF_B3 + i] = b3[i];
    for (int idx = tid; idx < 96 * 160; idx += 256) {
        int k = idx / 160, n = idx - k * 160;
        sh[k * 168 + n] = __float2half(w2[idx]);
    }
    for (int idx = tid; idx < 160 * 192; idx += 256) {
        int k = idx / 192, n = idx - k * 192;
        sh[BW3 / 2 + k * 200 + n] = __float2half(w3[idx]);
    }
    for (int idx = tid; idx < 5 * 52; idx += 256)
        s32[H1B32 + (75 + idx / 52) * 52 + (idx % 52)] = 0u;
    __syncthreads();

    const int nt1 = (wid < 4) ? 3 : 2;
    int n1[3], n2[3];
    #pragma unroll
    for (int j = 0; j < 3; j++) { n1[j] = 8 * wid + 64 * j; n2[j] = 8 * wid + 64 * j; }
    const int lA = lane & 15, gA = lane >> 4;
    const int lB = lane & 15;
    const int qr = lane >> 2, qc = lane & 3;
    const uint32_t a1base = sbase + BH1 + (uint32_t)(lA * 104 + gA * 8) * 2;
    const uint32_t a2base = sbase + BH2 + (uint32_t)(lA * 168 + gA * 8) * 2;
    const uint32_t b2base = sbase + BW2 + (uint32_t)(lB * 168) * 2;
    const uint32_t b3base = sbase + BW3 + (uint32_t)(lB * 200) * 2;
    float e1b0[3], e1b1[3], e2b0[3], e2b1[3];
    #pragma unroll
    for (int j = 0; j < 3; j++) {
        if (j < nt1) {
            e1b0[j] = s[OF_B2 + n1[j] + 2 * qc];
            e1b1[j] = s[OF_B2 + n1[j] + 2 * qc + 1];
        } else { e1b0[j] = 0.f; e1b1[j] = 0.f; }
        e2b0[j] = s[OF_B3 + n2[j] + 2 * qc];
        e2b1[j] = s[OF_B3 + n2[j] + 2 * qc + 1];
    }

    // ---- Hoist ALL loop-invariant B fragments into registers ----
    uint32_t bf2[6][3][2];
    uint32_t bf3[10][3][2];
    #pragma unroll
    for (int k = 0; k < 6; k++)
        #pragma unroll
        for (int j = 0; j < 3; j++) {
            if (j < nt1) { LDSM_X2T(bf2[k][j][0], bf2[k][j][1], b2base + k * 5376 + n1[j] * 2); }
            else { bf2[k][j][0] = 0u; bf2[k][j][1] = 0u; }
        }
    #pragma unroll
    for (int k = 0; k < 10; k++)
        #pragma unroll
        for (int j = 0; j < 3; j++)
            LDSM_X2T(bf3[k][j][0], bf3[k][j][1], b3base + k * 6400 + n2[j] * 2);

    for (int bi = blockIdx.x; bi < 9600; bi += gridDim.x) {
        const int b = bi / 75, i = bi % 75;
        const float* xb = x + b * 75 * 3;
        const float xi0 = xb[i * 3 + 0], xi1 = xb[i * 3 + 1], xi2 = xb[i * 3 + 2];

        if (tid < 75) {
            float a0 = xb[tid * 3 + 0], a1 = xb[tid * 3 + 1], a2 = xb[tid * 3 + 2];
            s[OF_XJ + 3 * tid + 0] = a0;
            s[OF_XJ + 3 * tid + 1] = a1;
            s[OF_XJ + 3 * tid + 2] = a2;
            float d0 = (a0 - xi0) + 1e-12f;
            float d1 = (a1 - xi1) + 1e-12f;
            float d2 = (a2 - xi2) + 1e-12f;
            s[OF_D + tid] = sqrtf(d0 * d0 + d1 * d1 + d2 * d2);
        }
        if (tid >= 160) {
            int c = tid - 160;
            s[OF_UI + c] = b1[c] + xi0 * s[OF_W1 + c]
                                 + xi1 * s[OF_W1 + 96 + c]
                                 + xi2 * s[OF_W1 + 192 + c];
        }
        __syncthreads();

        for (int idx = tid; idx < 75 * 48; idx += 256) {
            int r = idx / 48, w = idx - r * 48;
            float xj0 = s[OF_XJ + 3 * r + 0];
            float xj1 = s[OF_XJ + 3 * r + 1];
            float xj2 = s[OF_XJ + 3 * r + 2];
            float dj  = s[OF_D + r];
            unsigned long long v = *(const unsigned long long*)(s + OF_UI + 2 * w);
            FFMA2(v, pack2(xj0, xj0), *(const unsigned long long*)(s + OF_W1 + 288 + 2 * w));
            FFMA2(v, pack2(xj1, xj1), *(const unsigned long long*)(s + OF_W1 + 384 + 2 * w));
            FFMA2(v, pack2(xj2, xj2), *(const unsigned long long*)(s + OF_W1 + 480 + 2 * w));
            FFMA2(v, pack2(dj, dj),   *(const unsigned long long*)(s + OF_W1 + 576 + 2 * w));
            float2 vf = unpack2(v);
            s32[H1B32 + r * 52 + w] = cvt_f16x2(lrelu(vf.y), lrelu(vf.x));
        }
        __syncthreads();

        // ---- MMA1: D1[80][160] = h1 @ W2 ; epi -> h2 fp16 ----
        {
            float acc[5][3][4];
            #pragma unroll
            for (int m = 0; m < 5; m++)
                #pragma unroll
                for (int j = 0; j < 3; j++)
                    { acc[m][j][0]=0.f; acc[m][j][1]=0.f; acc[m][j][2]=0.f; acc[m][j][3]=0.f; }
            #pragma unroll
            for (int k = 0; k < 6; k++) {
                #pragma unroll
                for (int m = 0; m < 5; m++) {
                    uint32_t a0, a1, a2, a3;
                    LDSM_X4(a0, a1, a2, a3, a1base + m * 3328 + k * 32);
                    #pragma unroll
                    for (int j = 0; j < 3; j++)
                        if (j < nt1) MMA16816(acc[m][j], a0, a1, a2, a3, bf2[k][j][0], bf2[k][j][1]);
                }
            }
            #pragma unroll
            for (int m = 0; m < 5; m++) {
                int r1 = m * 16 + qr, r2 = r1 + 8;
                #pragma unroll
                for (int j = 0; j < 3; j++)
                    if (j < nt1) {
                        uint32_t u = n1[j] / 2 + qc;
                        s32[H2B32 + r1 * 84 + u] =
                            cvt_f16x2(lrelu(acc[m][j][1] + e1b1[j]),
                                      lrelu(acc[m][j][0] + e1b0[j]));
                        s32[H2B32 + r2 * 84 + u] =
                            cvt_f16x2(lrelu(acc[m][j][3] + e1b1[j]),
                                      lrelu(acc[m][j][2] + e1b0[j]));
                    }
            }
        }
        __syncthreads();

        // ---- MMA2: D2[80][192] = h2 @ W3 (B frags in registers) ----
        {
            float acc[5][3][4];
            #pragma unroll
            for (int m = 0; m < 5; m++)
                #pragma unroll
                for (int j = 0; j < 3; j++)
                    { acc[m][j][0]=0.f; acc[m][j][1]=0.f; acc[m][j][2]=0.f; acc[m][j][3]=0.f; }
            #pragma unroll
            for (int k = 0; k < 10; k++) {
                #pragma unroll
                for (int m = 0; m < 5; m++) {
                    uint32_t a0, a1, a2, a3;
                    LDSM_X4(a0, a1, a2, a3, a2base + m * 5376 + k * 32);
                    #pragma unroll
                    for (int j = 0; j < 3; j++)
                        MMA16816(acc[m][j], a0, a1, a2, a3, bf3[k][j][0], bf3[k][j][1]);
                }
            }
            float cs0[3] = {0.f, 0.f, 0.f}, cs1[3] = {0.f, 0.f, 0.f};
            #pragma unroll
            for (int m = 0; m < 5; m++) {
                bool ok2 = (m * 16 + 8 + qr) < 75;
                #pragma unroll
                for (int j = 0; j < 3; j++) {
                    cs0[j] += lrelu(acc[m][j][0] + e2b0[j]);
                    cs1[j] += lrelu(acc[m][j][1] + e2b1[j]);
                    if (ok2) {
                        cs0[j] += lrelu(acc[m][j][2] + e2b0[j]);
                        cs1[j] += lrelu(acc[m][j][3] + e2b1[j]);
                    }
                }
            }
            #pragma unroll
            for (int j = 0; j < 3; j++) {
                #pragma unroll
                for (int d = 4; d < 32; d <<= 1) {
                    cs0[j] += __shfl_xor_sync(0xFFFFFFFFu, cs0[j], d);
                    cs1[j] += __shfl_xor_sync(0xFFFFFFFFu, cs1[j], d);
                }
            }
            if (lane < 4) {
                float* gp = g_agg + bi * 192;
                #pragma unroll
                for (int j = 0; j < 3; j++) {
                    gp[n2[j] + 2 * lane]     = cs0[j];
                    gp[n2[j] + 2 * lane + 1] = cs1[j];
                }
            }
        }
        __syncthreads();
    }
}

// ================= NODE KERNEL — 80 rows/CTA, grid 120 (one wave) =================
// SMEM bytes:
//   BWN  = 0       weights region 135168 (holds W1 full 109824, then W2 full 135168)
//   BH1N = 135168  h1 80 x 264 halfs = 42240
//   BYN  = 177408  y 80 x 216 halfs (34560) / h2 80 x 264 halfs (42240) overlay
//   f32 at 219648 B
#define BWN   0
#define BH1N  135168
#define BYN   177408
#define OFN_B1 54912
#define OFN_B2 55168
#define OFN_W3 55424
#define OFN_B3 56192
#define SMEM2_FL 56196
#define SMEM2_BYTES (SMEM2_FL * 4)   // 224784
#define H1NU (BH1N / 4)
#define YNU  (BYN / 4)

__global__ void __launch_bounds__(256, 1)
node_kernel(const float* __restrict__ x,
            const float* __restrict__ b1,
            const float* __restrict__ b2,
            const float* __restrict__ w3, const float* __restrict__ b3,
            float* __restrict__ out)
{
    extern __shared__ float s[];
    uint32_t* s32 = (uint32_t*)s;
    __half* sh = (__half*)s;
    const int tid = threadIdx.x;
    const int wid = tid >> 5;
    const int lane = tid & 31;
    const uint32_t sbase = smem_u32(s);
    const int row0 = blockIdx.x * 80;

    const int lA = lane & 15, gA = lane >> 4;
    const int lB = lane & 15;
    const int qr = lane >> 2, qc = lane & 3;
    const int n0 = 32 * wid;
    const uint32_t aYbase  = sbase + BYN  + (uint32_t)(lA * 216 + gA * 8) * 2;
    const uint32_t aH1base = sbase + BH1N + (uint32_t)(lA * 264 + gA * 8) * 2;
    const uint32_t bWbase  = sbase + BWN  + (uint32_t)(lB * 264) * 2;

    // ---- Stage 0: biases/w3 + y tile + W1 fp16 (pure uint4 copy) ----
    for (int i = tid; i < 256; i += 256) s[OFN_B1 + i] = b1[i];
    for (int i = tid; i < 256; i += 256) s[OFN_B2 + i] = b2[i];
    for (int i = tid; i < 768; i += 256) s[OFN_W3 + i] = w3[i];
    if (tid < 3) s[OFN_B3 + tid] = b3[tid];

    for (int idx = tid; idx < 80 * 108; idx += 256) {
        int r = idx / 108, u = idx - r * 108;
        int gr = row0 + r;
        uint32_t v;
        if (u < 96) {
            const float* gp = g_agg + (size_t)gr * 192 + 2 * u;
            v = cvt_f16x2(gp[1], gp[0]);
        } else if (u == 96) {
            v = cvt_f16x2(x[gr * 3 + 1], x[gr * 3 + 0]);
        } else if (u == 97) {
            v = cvt_f16x2(0.f, x[gr * 3 + 2]);
        } else v = 0u;
        s32[YNU + r * 108 + u] = v;
    }
    {
        uint4* d = (uint4*)s32;
        for (int i = tid; i < 208 * 132 / 4; i += 256) d[i] = g_w1h[i];
    }
    __syncthreads();

    // ---- Phase 1: h1[80][256] = lrelu(y @ W1 + b1), K = 208 (13 chunks) ----
    {
        float acc[5][4][4];
        #pragma unroll
        for (int m = 0; m < 5; m++)
            #pragma unroll
            for (int j = 0; j < 4; j++)
                { acc[m][j][0]=0.f; acc[m][j][1]=0.f; acc[m][j][2]=0.f; acc[m][j][3]=0.f; }
        #pragma unroll
        for (int kc = 0; kc < 13; kc++) {
            uint32_t bf[4][2];
            #pragma unroll
            for (int j = 0; j < 4; j++)
                LDSM_X2T(bf[j][0], bf[j][1], bWbase + kc * 8448 + (n0 + 8 * j) * 2);
            #pragma unroll
            for (int m = 0; m < 5; m++) {
                uint32_t a0, a1, a2, a3;
                LDSM_X4(a0, a1, a2, a3, aYbase + m * 6912 + kc * 32);
                #pragma unroll
                for (int j = 0; j < 4; j++)
                    MMA16816(acc[m][j], a0, a1, a2, a3, bf[j][0], bf[j][1]);
            }
        }
        #pragma unroll
        for (int m = 0; m < 5; m++) {
            int r1 = m * 16 + qr, r2 = r1 + 8;
            #pragma unroll
            for (int j = 0; j < 4; j++) {
                float bb0 = s[OFN_B1 + n0 + 8 * j + 2 * qc];
                float bb1 = s[OFN_B1 + n0 + 8 * j + 2 * qc + 1];
                uint32_t u = n0 / 2 + 4 * j + qc;
                s32[H1NU + r1 * 132 + u] =
                    cvt_f16x2(lrelu(acc[m][j][1] + bb1), lrelu(acc[m][j][0] + bb0));
                s32[H1NU + r2 * 132 + u] =
                    cvt_f16x2(lrelu(acc[m][j][3] + bb1), lrelu(acc[m][j][2] + bb0));
            }
        }
    }
    __syncthreads();

    // ---- Stage: overwrite weights region with W2 fp16 (uint4 copy) ----
    {
        uint4* d = (uint4*)s32;
        for (int i = tid; i < 256 * 132 / 4; i += 256) d[i] = g_w2h[i];
    }
    __syncthreads();

    // ---- Phase 2: h2[80][256] = lrelu(h1 @ W2 + b2), K = 256 (16 chunks) ----
    {
        float acc[5][4][4];
        #pragma unroll
        for (int m = 0; m < 5; m++)
            #pragma unroll
            for (int j = 0; j < 4; j++)
                { acc[m][j][0]=0.f; acc[m][j][1]=0.f; acc[m][j][2]=0.f; acc[m][j][3]=0.f; }
        #pragma unroll
        for (int kc = 0; kc < 16; kc++) {
            uint32_t bf[4][2];
            #pragma unroll
            for (int j = 0; j < 4; j++)
                LDSM_X2T(bf[j][0], bf[j][1], bWbase + kc * 8448 + (n0 + 8 * j) * 2);
            #pragma unroll
            for (int m = 0; m < 5; m++) {
                uint32_t a0, a1, a2, a3;
                LDSM_X4(a0, a1, a2, a3, aH1base + m * 8448 + kc * 32);
                #pragma unroll
                for (int j = 0; j < 4; j++)
                    MMA16816(acc[m][j], a0, a1, a2, a3, bf[j][0], bf[j][1]);
            }
        }
        #pragma unroll
        for (int m = 0; m < 5; m++) {
            int r1 = m * 16 + qr, r2 = r1 + 8;
            #pragma unroll
            for (int j = 0; j < 4; j++) {
                float bb0 = s[OFN_B2 + n0 + 8 * j + 2 * qc];
                float bb1 = s[OFN_B2 + n0 + 8 * j + 2 * qc + 1];
                uint32_t u = n0 / 2 + 4 * j + qc;
                s32[YNU + r1 * 132 + u] =
                    cvt_f16x2(lrelu(acc[m][j][1] + bb1), lrelu(acc[m][j][0] + bb0));
                s32[YNU + r2 * 132 + u] =
                    cvt_f16x2(lrelu(acc[m][j][3] + bb1), lrelu(acc[m][j][2] + bb0));
            }
        }
    }
    __syncthreads();

    // ---- Phase 3: out[80][3] = h2 @ W3 + b3 (half2-paired fp32, 240 threads) ----
    if (tid < 240) {
        int r = tid / 3, o = tid - r * 3;
        const __half2* hr = (const __half2*)(sh + BYN / 2 + r * 264);
        float a = s[OFN_B3 + o];
        #pragma unroll 8
        for (int k2 = 0; k2 < 128; k2++) {
            float2 h = __half22float2(hr[k2]);
            a += h.x * s[OFN_W3 + 6 * k2 + o] + h.y * s[OFN_W3 + 6 * k2 + 3 + o];
        }
        out[(row0 + r) * 3 + o] = a;
    }
}

extern "C" void kernel_launch(void* const* d_in, const int* in_sizes, int n_in,
                              void* d_out, int out_size)
{
    const float* x    = (const float*)d_in[0];
    const float* few1 = (const float*)d_in[1];
    const float* feb1 = (const float*)d_in[2];
    const float* few2 = (const float*)d_in[3];
    const float* feb2 = (const float*)d_in[4];
    const float* few3 = (const float*)d_in[5];
    const float* feb3 = (const float*)d_in[6];
    const float* fnw1 = (const float*)d_in[7];
    const float* fnb1 = (const float*)d_in[8];
    const float* fnw2 = (const float*)d_in[9];
    const float* fnb2 = (const float*)d_in[10];
    const float* fnw3 = (const float*)d_in[11];
    const float* fnb3 = (const float*)d_in[12];
    float* out = (float*)d_out;

    cudaFuncSetAttribute(edge_kernel, cudaFuncAttributeMaxDynamicSharedMemorySize, SMEM1_BYTES);
    cudaFuncSetAttribute(node_kernel, cudaFuncAttributeMaxDynamicSharedMemorySize, SMEM2_BYTES);

    prep_kernel<<<132, 256>>>(fnw1, fnw2);
    edge_kernel<<<148, 256, SMEM1_BYTES>>>(x, few1, feb1, few2, feb2, few3, feb3);
    node_kernel<<<120, 256, SMEM2_BYTES>>>(x, fnb1, fnb2, fnw3, fnb3, out);
}

// round 13
// speedup vs baseline: 1.0451x; 1.0269x over previous
#include <cuda_runtime.h>
#include <cuda_fp16.h>
#include <cstdint>

#define ALPHA 0.2f

// Pre-converted fp16 node weights in tail-SMEM layout (u32 = f16x2, row stride 132 u32)
static __device__ uint4 g_w1h[208 * 132 / 4];   // 195x256 valid, zero-padded
static __device__ uint4 g_w2h[256 * 132 / 4];

__device__ __forceinline__ float lrelu(float v) { return v > 0.0f ? v : ALPHA * v; }

#define FFMA2(acc, a, b) \
    asm("fma.rn.f32x2 %0, %1, %2, %0;" : "+l"(acc) : "l"(a), "l"(b))
__device__ __forceinline__ float2 unpack2(unsigned long long v) {
    float2 r;
    asm("mov.b64 {%0, %1}, %2;" : "=f"(r.x), "=f"(r.y) : "l"(v));
    return r;
}
__device__ __forceinline__ unsigned long long pack2(float lo, float hi) {
    unsigned long long r;
    asm("mov.b64 %0, {%1, %2};" : "=l"(r) : "f"(lo), "f"(hi));
    return r;
}
__device__ __forceinline__ uint32_t cvt_f16x2(float hi, float lo) {
    uint32_t d;
    asm("cvt.rn.f16x2.f32 %0, %1, %2;" : "=r"(d) : "f"(hi), "f"(lo));
    return d;
}
__device__ __forceinline__ uint32_t smem_u32(const void* p) {
    uint32_t a;
    asm("{ .reg .u64 t; cvta.to.shared.u64 t, %1; cvt.u32.u64 %0, t; }"
        : "=r"(a) : "l"(p));
    return a;
}

#define LDSM_X4(a0, a1, a2, a3, addr) \
    asm volatile("ldmatrix.sync.aligned.m8n8.x4.shared.b16 {%0,%1,%2,%3}, [%4];" \
                 : "=r"(a0), "=r"(a1), "=r"(a2), "=r"(a3) : "r"(addr))
#define LDSM_X2T(b0, b1, addr) \
    asm volatile("ldmatrix.sync.aligned.m8n8.x2.trans.shared.b16 {%0,%1}, [%2];" \
                 : "=r"(b0), "=r"(b1) : "r"(addr))
#define MMA16816(c, a0, a1, a2, a3, b0, b1) \
    asm volatile("mma.sync.aligned.m16n8k16.row.col.f32.f16.f16.f32 " \
                 "{%0,%1,%2,%3}, {%4,%5,%6,%7}, {%8,%9}, {%0,%1,%2,%3};" \
                 : "+f"((c)[0]), "+f"((c)[1]), "+f"((c)[2]), "+f"((c)[3]) \
                 : "r"(a0), "r"(a1), "r"(a2), "r"(a3), "r"(b0), "r"(b1))

// ================= PREP KERNEL: fn weights -> fp16 layout =================
__global__ void __launch_bounds__(256)
prep_kernel(const float* __restrict__ w1, const float* __restrict__ w2)
{
    int i = blockIdx.x * 256 + threadIdx.x;
    if (i < 208 * 132) {
        int k = i / 132, u = i - k * 132;
        uint32_t v = 0u;
        if (k < 195 && u < 128)
            v = cvt_f16x2(w1[(size_t)k * 256 + 2 * u + 1], w1[(size_t)k * 256 + 2 * u]);
        ((uint32_t*)g_w1h)[i] = v;
    }
    if (i < 256 * 132) {
        int k = i / 132, u = i - k * 132;
        uint32_t v = 0u;
        if (u < 128)
            v = cvt_f16x2(w2[(size_t)k * 256 + 2 * u + 1], w2[(size_t)k * 256 + 2 * u]);
        ((uint32_t*)g_w2h)[i] = v;
    }
}

// ================= FUSED EDGE + NODE KERNEL =================
// SMEM byte layout:
//  [0,139776)       edge working set:  BW2 0, BW3 32256, BH1 96256, BH2 112896
//                   (tail overlays: W region [0,135168); h2 [0,42240) after ph2)
//  [139776,145472)  f32 region (edge: W1/B2/B3/UI/XJ/D; tail: b1n/b2n/w3n/b3n)
//  [145472,180032)  YT: y tile 80 rows x 216 halfs (persistent across edge loop)
//  [180032,222272)  H1T: tail h1 80 rows x 264 halfs
#define BW2 0
#define BW3 32256
#define BH1 96256
#define BH2 112896
#define OF_W1 34944   // float idx (byte 139776)
#define OF_B2 35616
#define OF_B3 35776
#define OF_UI 35968
#define OF_XJ 36064
#define OF_D  36292
#define BYT  145472
#define YTU  (BYT / 4)       // 36368
#define BH1T 180032
#define H1TU (BH1T / 4)      // 45008
// tail f32 (reuse edge f32 region)
#define OT_B1 34944
#define OT_B2 35200
#define OT_W3 35456
#define OT_B3 36224
#define SMEM1_BYTES 222272
#define H1B32 (BH1 / 4)
#define H2B32 (BH2 / 4)

__global__ void __launch_bounds__(256, 1)
edge_kernel(const float* __restrict__ x,
            const float* __restrict__ w1, const float* __restrict__ b1,
            const float* __restrict__ w2, const float* __restrict__ b2,
            const float* __restrict__ w3, const float* __restrict__ b3,
            const float* __restrict__ nb1, const float* __restrict__ nb2,
            const float* __restrict__ nw3, const float* __restrict__ nb3,
            float* __restrict__ out)
{
    extern __shared__ float s[];
    uint32_t* s32 = (uint32_t*)s;
    __half* sh = (__half*)s;
    const int tid = threadIdx.x;
    const int wid = tid >> 5;
    const int lane = tid & 31;
    const uint32_t sbase = smem_u32(s);

    // ---- one-time init ----
    for (int i = tid; i < 672; i += 256) s[OF_W1 + i] = w1[i];
    for (int i = tid; i < 160; i += 256) s[OF_B2 + i] = b2[i];
    for (int i = tid; i < 192; i += 256) s[OF_B3 + i] = b3[i];
    for (int idx = tid; idx < 96 * 160; idx += 256) {
        int k = idx / 160, n = idx - k * 160;
        sh[k * 168 + n] = __float2half(w2[idx]);
    }
    for (int idx = tid; idx < 160 * 192; idx += 256) {
        int k = idx / 192, n = idx - k * 192;
        sh[BW3 / 2 + k * 200 + n] = __float2half(w3[idx]);
    }
    for (int idx = tid; idx < 5 * 52; idx += 256)
        s32[H1B32 + (75 + idx / 52) * 52 + (idx % 52)] = 0u;
    // zero y tile (pad cols 195..215 and pad rows stay zero)
    for (int idx = tid; idx < 80 * 108; idx += 256) s32[YTU + idx] = 0u;
    __syncthreads();

    const int nt1 = (wid < 4) ? 3 : 2;
    int n1[3], n2[3];
    #pragma unroll
    for (int j = 0; j < 3; j++) { n1[j] = 8 * wid + 64 * j; n2[j] = 8 * wid + 64 * j; }
    const int lA = lane & 15, gA = lane >> 4;
    const int lB = lane & 15;
    const int qr = lane >> 2, qc = lane & 3;
    const uint32_t a1base = sbase + BH1 + (uint32_t)(lA * 104 + gA * 8) * 2;
    const uint32_t a2base = sbase + BH2 + (uint32_t)(lA * 168 + gA * 8) * 2;
    const uint32_t b2base = sbase + BW2 + (uint32_t)(lB * 168) * 2;
    const uint32_t b3base = sbase + BW3 + (uint32_t)(lB * 200) * 2;
    float e1b0[3], e1b1[3], e2b0[3], e2b1[3];
    #pragma unroll
    for (int j = 0; j < 3; j++) {
        if (j < nt1) {
            e1b0[j] = s[OF_B2 + n1[j] + 2 * qc];
            e1b1[j] = s[OF_B2 + n1[j] + 2 * qc + 1];
        } else { e1b0[j] = 0.f; e1b1[j] = 0.f; }
        e2b0[j] = s[OF_B3 + n2[j] + 2 * qc];
        e2b1[j] = s[OF_B3 + n2[j] + 2 * qc + 1];
    }

    // ---- hoist loop-invariant B fragments ----
    uint32_t bf2[6][3][2];
    uint32_t bf3[10][3][2];
    #pragma unroll
    for (int k = 0; k < 6; k++)
        #pragma unroll
        for (int j = 0; j < 3; j++) {
            if (j < nt1) { LDSM_X2T(bf2[k][j][0], bf2[k][j][1], b2base + k * 5376 + n1[j] * 2); }
            else { bf2[k][j][0] = 0u; bf2[k][j][1] = 0u; }
        }
    #pragma unroll
    for (int k = 0; k < 10; k++)
        #pragma unroll
        for (int j = 0; j < 3; j++)
            LDSM_X2T(bf3[k][j][0], bf3[k][j][1], b3base + k * 6400 + n2[j] * 2);

    // ================= EDGE LOOP =================
    int slot = 0;
    for (int bi = blockIdx.x; bi < 9600; bi += 148, slot++) {
        const int b = bi / 75, i = bi % 75;
        const float* xb = x + b * 75 * 3;
        const float xi0 = xb[i * 3 + 0], xi1 = xb[i * 3 + 1], xi2 = xb[i * 3 + 2];

        if (tid < 75) {
            float a0 = xb[tid * 3 + 0], a1 = xb[tid * 3 + 1], a2 = xb[tid * 3 + 2];
            s[OF_XJ + 3 * tid + 0] = a0;
            s[OF_XJ + 3 * tid + 1] = a1;
            s[OF_XJ + 3 * tid + 2] = a2;
            float d0 = (a0 - xi0) + 1e-12f;
            float d1 = (a1 - xi1) + 1e-12f;
            float d2 = (a2 - xi2) + 1e-12f;
            s[OF_D + tid] = sqrtf(d0 * d0 + d1 * d1 + d2 * d2);
        }
        if (tid < 3)  // y cols 192..194 = x[bi]
            sh[BYT / 2 + slot * 216 + 192 + tid] = __float2half(xb[i * 3 + tid]);
        if (tid >= 160) {
            int c = tid - 160;
            s[OF_UI + c] = b1[c] + xi0 * s[OF_W1 + c]
                                 + xi1 * s[OF_W1 + 96 + c]
                                 + xi2 * s[OF_W1 + 192 + c];
        }
        __syncthreads();

        for (int idx = tid; idx < 75 * 48; idx += 256) {
            int r = idx / 48, w = idx - r * 48;
            float xj0 = s[OF_XJ + 3 * r + 0];
            float xj1 = s[OF_XJ + 3 * r + 1];
            float xj2 = s[OF_XJ + 3 * r + 2];
            float dj  = s[OF_D + r];
            unsigned long long v = *(const unsigned long long*)(s + OF_UI + 2 * w);
            FFMA2(v, pack2(xj0, xj0), *(const unsigned long long*)(s + OF_W1 + 288 + 2 * w));
            FFMA2(v, pack2(xj1, xj1), *(const unsigned long long*)(s + OF_W1 + 384 + 2 * w));
            FFMA2(v, pack2(xj2, xj2), *(const unsigned long long*)(s + OF_W1 + 480 + 2 * w));
            FFMA2(v, pack2(dj, dj),   *(const unsigned long long*)(s + OF_W1 + 576 + 2 * w));
            float2 vf = unpack2(v);
            s32[H1B32 + r * 52 + w] = cvt_f16x2(lrelu(vf.y), lrelu(vf.x));
        }
        __syncthreads();

        // MMA1: h2 = lrelu(h1 @ W2 + b2)
        {
            float acc[5][3][4];
            #pragma unroll
            for (int m = 0; m < 5; m++)
                #pragma unroll
                for (int j = 0; j < 3; j++)
                    { acc[m][j][0]=0.f; acc[m][j][1]=0.f; acc[m][j][2]=0.f; acc[m][j][3]=0.f; }
            #pragma unroll
            for (int k = 0; k < 6; k++) {
                #pragma unroll
                for (int m = 0; m < 5; m++) {
                    uint32_t a0, a1, a2, a3;
                    LDSM_X4(a0, a1, a2, a3, a1base + m * 3328 + k * 32);
                    #pragma unroll
                    for (int j = 0; j < 3; j++)
                        if (j < nt1) MMA16816(acc[m][j], a0, a1, a2, a3, bf2[k][j][0], bf2[k][j][1]);
                }
            }
            #pragma unroll
            for (int m = 0; m < 5; m++) {
                int r1 = m * 16 + qr, r2 = r1 + 8;
                #pragma unroll
                for (int j = 0; j < 3; j++)
                    if (j < nt1) {
                        uint32_t u = n1[j] / 2 + qc;
                        s32[H2B32 + r1 * 84 + u] =
                            cvt_f16x2(lrelu(acc[m][j][1] + e1b1[j]),
                                      lrelu(acc[m][j][0] + e1b0[j]));
                        s32[H2B32 + r2 * 84 + u] =
                            cvt_f16x2(lrelu(acc[m][j][3] + e1b1[j]),
                                      lrelu(acc[m][j][2] + e1b0[j]));
                    }
            }
        }
        __syncthreads();

        // MMA2: column sums of lrelu(h2 @ W3 + b3) -> y tile (fp16)
        {
            float acc[5][3][4];
            #pragma unroll
            for (int m = 0; m < 5; m++)
                #pragma unroll
                for (int j = 0; j < 3; j++)
                    { acc[m][j][0]=0.f; acc[m][j][1]=0.f; acc[m][j][2]=0.f; acc[m][j][3]=0.f; }
            #pragma unroll
            for (int k = 0; k < 10; k++) {
                #pragma unroll
                for (int m = 0; m < 5; m++) {
                    uint32_t a0, a1, a2, a3;
                    LDSM_X4(a0, a1, a2, a3, a2base + m * 5376 + k * 32);
                    #pragma unroll
                    for (int j = 0; j < 3; j++)
                        MMA16816(acc[m][j], a0, a1, a2, a3, bf3[k][j][0], bf3[k][j][1]);
                }
            }
            float cs0[3] = {0.f, 0.f, 0.f}, cs1[3] = {0.f, 0.f, 0.f};
            #pragma unroll
            for (int m = 0; m < 5; m++) {
                bool ok2 = (m * 16 + 8 + qr) < 75;
                #pragma unroll
                for (int j = 0; j < 3; j++) {
                    cs0[j] += lrelu(acc[m][j][0] + e2b0[j]);
                    cs1[j] += lrelu(acc[m][j][1] + e2b1[j]);
                    if (ok2) {
                        cs0[j] += lrelu(acc[m][j][2] + e2b0[j]);
                        cs1[j] += lrelu(acc[m][j][3] + e2b1[j]);
                    }
                }
            }
            #pragma unroll
            for (int j = 0; j < 3; j++) {
                #pragma unroll
                for (int d = 4; d < 32; d <<= 1) {
                    cs0[j] += __shfl_xor_sync(0xFFFFFFFFu, cs0[j], d);
                    cs1[j] += __shfl_xor_sync(0xFFFFFFFFu, cs1[j], d);
                }
            }
            if (lane < 4) {
                #pragma unroll
                for (int j = 0; j < 3; j++)
                    s32[YTU + slot * 108 + n2[j] / 2 + lane] = cvt_f16x2(cs1[j], cs0[j]);
            }
        }
        __syncthreads();
    }

    // ================= NODE TAIL (this CTA's own rows) =================
    const int nslots = (blockIdx.x < 128) ? 65 : 64;
    const int n0 = 32 * wid;
    const uint32_t aYbase  = sbase + BYT  + (uint32_t)(lA * 216 + gA * 8) * 2;
    const uint32_t aH1base = sbase + BH1T + (uint32_t)(lA * 264 + gA * 8) * 2;
    const uint32_t bWbase  = sbase + (uint32_t)(lB * 264) * 2;

    for (int i = tid; i < 256; i += 256) s[OT_B1 + i] = nb1[i];
    for (int i = tid; i < 256; i += 256) s[OT_B2 + i] = nb2[i];
    for (int i = tid; i < 768; i += 256) s[OT_W3 + i] = nw3[i];
    if (tid < 3) s[OT_B3 + tid] = nb3[tid];
    {
        uint4* d = (uint4*)s32;
        for (int i = tid; i < 208 * 132 / 4; i += 256) d[i] = g_w1h[i];
    }
    __syncthreads();

    // ---- Tail phase 1: h1[80][256] = lrelu(y @ W1 + b1), K=208 ----
    {
        float acc[5][4][4];
        #pragma unroll
        for (int m = 0; m < 5; m++)
            #pragma unroll
            for (int j = 0; j < 4; j++)
                { acc[m][j][0]=0.f; acc[m][j][1]=0.f; acc[m][j][2]=0.f; acc[m][j][3]=0.f; }
        #pragma unroll
        for (int kc = 0; kc < 13; kc++) {
            uint32_t bf[4][2];
            #pragma unroll
            for (int j = 0; j < 4; j++)
                LDSM_X2T(bf[j][0], bf[j][1], bWbase + kc * 8448 + (n0 + 8 * j) * 2);
            #pragma unroll
            for (int m = 0; m < 5; m++) {
                uint32_t a0, a1, a2, a3;
                LDSM_X4(a0, a1, a2, a3, aYbase + m * 6912 + kc * 32);
                #pragma unroll
                for (int j = 0; j < 4; j++)
                    MMA16816(acc[m][j], a0, a1, a2, a3, bf[j][0], bf[j][1]);
            }
        }
        #pragma unroll
        for (int m = 0; m < 5; m++) {
            int r1 = m * 16 + qr, r2 = r1 + 8;
            #pragma unroll
            for (int j = 0; j < 4; j++) {
                float bb0 = s[OT_B1 + n0 + 8 * j + 2 * qc];
                float bb1 = s[OT_B1 + n0 + 8 * j + 2 * qc + 1];
                uint32_t u = n0 / 2 + 4 * j + qc;
                s32[H1TU + r1 * 132 + u] =
                    cvt_f16x2(lrelu(acc[m][j][1] + bb1), lrelu(acc[m][j][0] + bb0));
                s32[H1TU + r2 * 132 + u] =
                    cvt_f16x2(lrelu(acc[m][j][3] + bb1), lrelu(acc[m][j][2] + bb0));
            }
        }
    }
    __syncthreads();

    // ---- Stage W2 over the W region ----
    {
        uint4* d = (uint4*)s32;
        for (int i = tid; i < 256 * 132 / 4; i += 256) d[i] = g_w2h[i];
    }
    __syncthreads();

    // ---- Tail phase 2: h2 = lrelu(h1 @ W2 + b2), K=256; park h2 in W region ----
    {
        float acc[5][4][4];
        #pragma unroll
        for (int m = 0; m < 5; m++)
            #pragma unroll
            for (int j = 0; j < 4; j++)
                { acc[m][j][0]=0.f; acc[m][j][1]=0.f; acc[m][j][2]=0.f; acc[m][j][3]=0.f; }
        #pragma unroll
        for (int kc = 0; kc < 16; kc++) {
            uint32_t bf[4][2];
            #pragma unroll
            for (int j = 0; j < 4; j++)
                LDSM_X2T(bf[j][0], bf[j][1], bWbase + kc * 8448 + (n0 + 8 * j) * 2);
            #pragma unroll
            for (int m = 0; m < 5; m++) {
                uint32_t a0, a1, a2, a3;
                LDSM_X4(a0, a1, a2, a3, aH1base + m * 8448 + kc * 32);
                #pragma unroll
                for (int j = 0; j < 4; j++)
                    MMA16816(acc[m][j], a0, a1, a2, a3, bf[j][0], bf[j][1]);
            }
        }
        __syncthreads();   // all W2 reads done before overwriting W region with h2
        #pragma unroll
        for (int m = 0; m < 5; m++) {
            int r1 = m * 16 + qr, r2 = r1 + 8;
            #pragma unroll
            for (int j = 0; j < 4; j++) {
                float bb0 = s[OT_B2 + n0 + 8 * j + 2 * qc];
                float bb1 = s[OT_B2 + n0 + 8 * j + 2 * qc + 1];
                uint32_t u = n0 / 2 + 4 * j + qc;
                s32[r1 * 132 + u] =
                    cvt_f16x2(lrelu(acc[m][j][1] + bb1), lrelu(acc[m][j][0] + bb0));
                s32[r2 * 132 + u] =
                    cvt_f16x2(lrelu(acc[m][j][3] + bb1), lrelu(acc[m][j][2] + bb0));
            }
        }
    }
    __syncthreads();

    // ---- Tail phase 3: out[slot][3] = h2 @ W3 + b3 ----
    if (tid < 240) {
        int r = tid / 3, o = tid - r * 3;
        if (r < nslots) {
            const __half2* hr = (const __half2*)(sh + r * 264);
            float a = s[OT_B3 + o];
            #pragma unroll 8
            for (int k2 = 0; k2 < 128; k2++) {
                float2 h = __half22float2(hr[k2]);
                a += h.x * s[OT_W3 + 6 * k2 + o] + h.y * s[OT_W3 + 6 * k2 + 3 + o];
            }
            out[(blockIdx.x + r * 148) * 3 + o] = a;
        }
    }
}

extern "C" void kernel_launch(void* const* d_in, const int* in_sizes, int n_in,
                              void* d_out, int out_size)
{
    const float* x    = (const float*)d_in[0];
    const float* few1 = (const float*)d_in[1];
    const float* feb1 = (const float*)d_in[2];
    const float* few2 = (const float*)d_in[3];
    const float* feb2 = (const float*)d_in[4];
    const float* few3 = (const float*)d_in[5];
    const float* feb3 = (const float*)d_in[6];
    const float* fnw1 = (const float*)d_in[7];
    const float* fnb1 = (const float*)d_in[8];
    const float* fnw2 = (const float*)d_in[9];
    const float* fnb2 = (const float*)d_in[10];
    const float* fnw3 = (const float*)d_in[11];
    const float* fnb3 = (const float*)d_in[12];
    float* out = (float*)d_out;

    cudaFuncSetAttribute(edge_kernel, cudaFuncAttributeMaxDynamicSharedMemorySize, SMEM1_BYTES);

    prep_kernel<<<132, 256>>>(fnw1, fnw2);
    edge_kernel<<<148, 256, SMEM1_BYTES>>>(x, few1, feb1, few2, feb2, few3, feb3,
                                           fnb1, fnb2, fnw3, fnb3, out);
}